// round 6
// baseline (speedup 1.0000x reference)
#include <cuda_runtime.h>

#define BB 4
#define TT 16
#define HH 64
#define WW 64
#define CC 32
#define FF 64
#define OC 256   // 4*F
#define SP 325   // shared plane stride (== 5 mod 32 -> conflict-free)

// ---------------- scratch (device globals; no allocations allowed) ----------
__device__ float g_xn[(size_t)BB*TT*HH*WW*CC];
__device__ float g_zx[(size_t)BB*TT*HH*WW*OC];
__device__ float g_h [(size_t)BB*HH*WW*FF];
__device__ float g_c [(size_t)BB*HH*WW*FF];
__device__ float g_z [(size_t)BB*HH*WW*OC];

// ---------------- LayerNorm over channel axis (C=32 = one warp) -------------
__global__ void ln_kernel(const float* __restrict__ x,
                          const float* __restrict__ gamma,
                          const float* __restrict__ beta) {
    int row  = blockIdx.x * 8 + (threadIdx.x >> 5);
    int lane = threadIdx.x & 31;
    float v = x[(size_t)row * CC + lane];
    float s = v, s2 = v * v;
    #pragma unroll
    for (int o = 16; o; o >>= 1) {
        s  += __shfl_xor_sync(0xffffffffu, s,  o);
        s2 += __shfl_xor_sync(0xffffffffu, s2, o);
    }
    float mu  = s * (1.f / 32.f);
    float var = s2 * (1.f / 32.f) - mu * mu;
    float inv = rsqrtf(var + 1e-3f);
    g_xn[(size_t)row * CC + lane] = (v - mu) * inv * gamma[lane] + beta[lane];
}

// ---------------- zero h, c --------------------------------------------------
__global__ void zero_hc_kernel() {
    int i = blockIdx.x * blockDim.x + threadIdx.x;
    if (i < BB * HH * WW * FF) { g_h[i] = 0.f; g_c[i] = 0.f; }
}

// ---------------- input conv: zx = conv3x3(xn, Wx) + b ----------------------
// grid: (ocb=8, tile=16, bt=64), block 256.  Tile 16x16, 32 out channels.
// Weights read via LDG (uniform broadcast -> L1-resident), smem = input only.
__global__ __launch_bounds__(256, 3) void convx_kernel(const float* __restrict__ Wx,
                                                       const float* __restrict__ bias) {
    extern __shared__ float s_in[];   // CC * SP floats = 41.6KB

    int ocb  = blockIdx.x;
    int tile = blockIdx.y;
    int bt   = blockIdx.z;
    int tid  = threadIdx.x;
    int ty0 = (tile >> 2) * 16, tx0 = (tile & 3) * 16;
    int oc0 = ocb * 32;

    const float* xin = g_xn + (size_t)bt * HH * WW * CC;
    for (int i = tid; i < CC * 324; i += 256) {
        int ch = i / 324, sp = i - ch * 324;
        int gy = ty0 - 1 + sp / 18, gx = tx0 - 1 + sp % 18;
        float v = 0.f;
        if (gy >= 0 && gy < HH && gx >= 0 && gx < WW)
            v = xin[((size_t)gy * WW + gx) * CC + ch];
        s_in[ch * SP + sp] = v;
    }
    __syncthreads();

    int px = tid & 15, py = tid >> 4;
    float acc[32];
    #pragma unroll
    for (int oc = 0; oc < 32; oc++) acc[oc] = bias[oc0 + oc];

    #pragma unroll
    for (int kp = 0; kp < 9; kp++) {
        int ky = kp / 3, kx = kp - 3 * ky;
        int spb = (py + ky) * 18 + px + kx;
        const float4* wrow = (const float4*)(Wx + (size_t)kp * CC * OC + oc0);
        #pragma unroll 4
        for (int ic = 0; ic < CC; ic++) {
            float a = s_in[ic * SP + spb];
            const float4* w4 = wrow + ic * (OC / 4);
            #pragma unroll
            for (int j = 0; j < 8; j++) {
                float4 w = __ldg(w4 + j);
                acc[4*j+0] += a * w.x; acc[4*j+1] += a * w.y;
                acc[4*j+2] += a * w.z; acc[4*j+3] += a * w.w;
            }
        }
    }
    float* zp = g_zx + ((((size_t)bt) * HH + ty0 + py) * WW + tx0 + px) * OC + oc0;
    #pragma unroll
    for (int j = 0; j < 8; j++)
        ((float4*)zp)[j] = make_float4(acc[4*j], acc[4*j+1], acc[4*j+2], acc[4*j+3]);
}

// ---------------- recurrent conv: z = zx[:,t] + conv3x3(h, Wh) --------------
// grid: (ocb=8, tile=16, b=4), block 256.  Weights via LDG/L1; smem = h tile.
__global__ __launch_bounds__(256, 2) void convh_kernel(const float* __restrict__ Wh, int t) {
    extern __shared__ float s_in[];   // FF * SP floats = 83.2KB

    int ocb  = blockIdx.x;
    int tile = blockIdx.y;
    int b    = blockIdx.z;
    int tid  = threadIdx.x;
    int ty0 = (tile >> 2) * 16, tx0 = (tile & 3) * 16;
    int oc0 = ocb * 32;

    const float* hin = g_h + (size_t)b * HH * WW * FF;
    for (int i = tid; i < FF * 324; i += 256) {
        int ch = i / 324, sp = i - ch * 324;
        int gy = ty0 - 1 + sp / 18, gx = tx0 - 1 + sp % 18;
        float v = 0.f;
        if (gy >= 0 && gy < HH && gx >= 0 && gx < WW)
            v = hin[((size_t)gy * WW + gx) * FF + ch];
        s_in[ch * SP + sp] = v;
    }
    __syncthreads();

    int px = tid & 15, py = tid >> 4;
    int y = ty0 + py, x = tx0 + px;

    float acc[32];
    const float4* zx4 = (const float4*)(g_zx +
        (((((size_t)b * TT) + t) * HH + y) * WW + x) * OC + oc0);
    #pragma unroll
    for (int j = 0; j < 8; j++) {
        float4 v = zx4[j];
        acc[4*j+0] = v.x; acc[4*j+1] = v.y; acc[4*j+2] = v.z; acc[4*j+3] = v.w;
    }

    #pragma unroll
    for (int kp = 0; kp < 9; kp++) {
        int ky = kp / 3, kx = kp - 3 * ky;
        int spb = (py + ky) * 18 + px + kx;
        const float4* wrow = (const float4*)(Wh + (size_t)kp * FF * OC + oc0);
        #pragma unroll 4
        for (int ic = 0; ic < FF; ic++) {
            float a = s_in[ic * SP + spb];
            const float4* w4 = wrow + ic * (OC / 4);
            #pragma unroll
            for (int j = 0; j < 8; j++) {
                float4 w = __ldg(w4 + j);
                acc[4*j+0] += a * w.x; acc[4*j+1] += a * w.y;
                acc[4*j+2] += a * w.z; acc[4*j+3] += a * w.w;
            }
        }
    }
    float* zp = g_z + (((size_t)b * HH + y) * WW + x) * OC + oc0;
    #pragma unroll
    for (int j = 0; j < 8; j++)
        ((float4*)zp)[j] = make_float4(acc[4*j], acc[4*j+1], acc[4*j+2], acc[4*j+3]);
}

// ---------------- LSTM gates + MaxPool(2x2) fused ---------------------------
// One thread handles a 2x2 pixel quad for one feature f: computes c,h for all
// four pixels, writes h (needed by next conv) and the pooled output.
__global__ void gatepool_kernel(float* __restrict__ out, int t) {
    int i = blockIdx.x * blockDim.x + threadIdx.x;   // B*32*32*F = 262144
    if (i >= BB * 32 * 32 * FF) return;
    int f = i & 63;
    int r = i >> 6;
    int xo = r & 31; r >>= 5;
    int yo = r & 31;
    int b  = r >> 5;

    float m = -1e30f;
    #pragma unroll
    for (int dy = 0; dy < 2; dy++) {
        #pragma unroll
        for (int dx = 0; dx < 2; dx++) {
            size_t pix = ((size_t)b * HH + (yo * 2 + dy)) * WW + (xo * 2 + dx);
            const float* z = g_z + pix * OC;
            float zi = z[f], zf = z[64 + f], zc = z[128 + f], zo_ = z[192 + f];
            float ig = __saturatef(0.2f * zi + 0.5f);
            float fg = __saturatef(0.2f * zf + 0.5f);
            float og = __saturatef(0.2f * zo_ + 0.5f);
            size_t hi = pix * FF + f;
            float c  = fg * g_c[hi] + ig * tanhf(zc);
            g_c[hi] = c;
            float h = og * tanhf(c);
            g_h[hi] = h;
            m = fmaxf(m, h);
        }
    }
    out[(((((size_t)b * TT) + t) * 32 + yo) * 32 + xo) * FF + f] = m;
}

// ---------------- launch ----------------------------------------------------
extern "C" void kernel_launch(void* const* d_in, const int* in_sizes, int n_in,
                              void* d_out, int out_size) {
    const float* x     = (const float*)d_in[0];
    const float* gamma = (const float*)d_in[1];
    const float* beta  = (const float*)d_in[2];
    const float* Wx    = (const float*)d_in[3];
    const float* Wh    = (const float*)d_in[4];
    const float* bias  = (const float*)d_in[5];
    float* out = (float*)d_out;

    const int SMEM_X = CC * SP * 4;   // 41600 B
    const int SMEM_H = FF * SP * 4;   // 83200 B
    cudaFuncSetAttribute(convx_kernel, cudaFuncAttributeMaxDynamicSharedMemorySize, SMEM_X);
    cudaFuncSetAttribute(convh_kernel, cudaFuncAttributeMaxDynamicSharedMemorySize, SMEM_H);

    // LayerNorm
    ln_kernel<<<(BB * TT * HH * WW) / 8, 256>>>(x, gamma, beta);

    // zero h, c (must happen every call: deterministic)
    zero_hc_kernel<<<(BB * HH * WW * FF + 255) / 256, 256>>>();

    // input conv over all timesteps at once
    convx_kernel<<<dim3(8, 16, BB * TT), 256, SMEM_X>>>(Wx, bias);

    // recurrent loop
    for (int t = 0; t < TT; t++) {
        convh_kernel<<<dim3(8, 16, BB), 256, SMEM_H>>>(Wh, t);
        gatepool_kernel<<<(BB * 32 * 32 * FF + 255) / 256, 256>>>(out, t);
    }
}

// round 7
// speedup vs baseline: 2.6747x; 2.6747x over previous
#include <cuda_runtime.h>

#define BB 4
#define TT 16
#define HH 64
#define WW 64
#define CC 32
#define FF 64
#define OC 256   // 4*F
#define PS 613   // smem plane stride (odd mod 32 -> conflict-free chunk loads)
#define HALO 612 // 18*34 halo plane elements

// ---------------- scratch (device globals; no allocations allowed) ----------
__device__ float g_xn[(size_t)BB*TT*HH*WW*CC];
__device__ float g_zx[(size_t)BB*TT*HH*WW*OC];
__device__ float g_h [(size_t)BB*HH*WW*FF];
__device__ float g_c [(size_t)BB*HH*WW*FF];
__device__ float g_z [(size_t)BB*HH*WW*OC];

// ---------------- LayerNorm over channel axis (C=32 = one warp) -------------
__global__ void ln_kernel(const float* __restrict__ x,
                          const float* __restrict__ gamma,
                          const float* __restrict__ beta) {
    int row  = blockIdx.x * 8 + (threadIdx.x >> 5);
    int lane = threadIdx.x & 31;
    float v = x[(size_t)row * CC + lane];
    float s = v, s2 = v * v;
    #pragma unroll
    for (int o = 16; o; o >>= 1) {
        s  += __shfl_xor_sync(0xffffffffu, s,  o);
        s2 += __shfl_xor_sync(0xffffffffu, s2, o);
    }
    float mu  = s * (1.f / 32.f);
    float var = s2 * (1.f / 32.f) - mu * mu;
    float inv = rsqrtf(var + 1e-3f);
    g_xn[(size_t)row * CC + lane] = (v - mu) * inv * gamma[lane] + beta[lane];
}

// ---------------- zero h, c --------------------------------------------------
__global__ void zero_hc_kernel() {
    int i = blockIdx.x * blockDim.x + threadIdx.x;
    if (i < BB * HH * WW * FF) { g_h[i] = 0.f; g_c[i] = 0.f; }
}

// ============================================================================
// Conv template notes (both convs):
//   block = 256 threads, tile = 32 wide x 16 tall, 2 pixels/thread (y, y+8),
//   32 out channels per block, input channels processed in chunks of 32.
//   smem = input chunk [32][613] + weight chunk [9][32][32] = 115328 B
//   -> 2 CTAs/SM, 16 warps.  Inner iter: 2 LDS + 8 LDS.128 + 64 FFMA.
// ============================================================================

// ---------------- input conv: zx = conv3x3(xn, Wx) + b ----------------------
// grid: (ocb=8, tile=8, bt=64)
__global__ __launch_bounds__(256, 2) void convx_kernel(const float* __restrict__ Wx,
                                                       const float* __restrict__ bias) {
    extern __shared__ float sm[];
    float* s_in = sm;                 // 32 * 613
    float* s_w  = sm + 32 * PS;       // 9216

    int ocb  = blockIdx.x;
    int tile = blockIdx.y;
    int bt   = blockIdx.z;
    int tid  = threadIdx.x;
    int ty0 = (tile >> 1) * 16, tx0 = (tile & 1) * 32;
    int oc0 = ocb * 32;
    int px = tid & 31, py = tid >> 5;
    int y1 = ty0 + py, y2 = y1 + 8, x = tx0 + px;

    const float* xin = g_xn + (size_t)bt * HH * WW * CC;

    // load input chunk (all CC=32 channels), float4 over channels, coalesced
    for (int i = tid; i < 8 * HALO; i += 256) {
        int c4 = (i & 7) * 4, sp = i >> 3;
        int ry = sp / 34, rx = sp - ry * 34;
        int gy = ty0 - 1 + ry, gx = tx0 - 1 + rx;
        float4 v = make_float4(0.f, 0.f, 0.f, 0.f);
        if (gy >= 0 && gy < HH && gx >= 0 && gx < WW)
            v = *(const float4*)(xin + ((size_t)gy * WW + gx) * CC + c4);
        s_in[(c4+0)*PS + sp] = v.x; s_in[(c4+1)*PS + sp] = v.y;
        s_in[(c4+2)*PS + sp] = v.z; s_in[(c4+3)*PS + sp] = v.w;
    }
    // load weight chunk [kp][ic][oc32]
    for (int i = tid; i < 9 * CC * 32; i += 256) {
        int oc = i & 31, rest = i >> 5;          // rest = kp*32 + ic
        s_w[i] = Wx[(size_t)rest * OC + oc0 + oc];
    }
    __syncthreads();

    float acc1[32], acc2[32];
    #pragma unroll
    for (int oc = 0; oc < 32; oc++) { float bv = bias[oc0 + oc]; acc1[oc] = bv; acc2[oc] = bv; }

    #pragma unroll
    for (int kp = 0; kp < 9; kp++) {
        int ky = kp / 3, kx = kp - 3 * ky;
        int spb = (py + ky) * 34 + px + kx;
        const float* wk = s_w + kp * 1024;
        #pragma unroll 4
        for (int ic = 0; ic < CC; ic++) {
            float a1 = s_in[ic * PS + spb];
            float a2 = s_in[ic * PS + spb + 272];     // +8 rows
            const float4* w4 = (const float4*)(wk + ic * 32);
            #pragma unroll
            for (int j = 0; j < 8; j++) {
                float4 w = w4[j];
                acc1[4*j+0] += a1 * w.x; acc1[4*j+1] += a1 * w.y;
                acc1[4*j+2] += a1 * w.z; acc1[4*j+3] += a1 * w.w;
                acc2[4*j+0] += a2 * w.x; acc2[4*j+1] += a2 * w.y;
                acc2[4*j+2] += a2 * w.z; acc2[4*j+3] += a2 * w.w;
            }
        }
    }
    float* o1 = g_zx + (((size_t)bt * HH + y1) * WW + x) * OC + oc0;
    float* o2 = g_zx + (((size_t)bt * HH + y2) * WW + x) * OC + oc0;
    #pragma unroll
    for (int j = 0; j < 8; j++) {
        ((float4*)o1)[j] = make_float4(acc1[4*j], acc1[4*j+1], acc1[4*j+2], acc1[4*j+3]);
        ((float4*)o2)[j] = make_float4(acc2[4*j], acc2[4*j+1], acc2[4*j+2], acc2[4*j+3]);
    }
}

// ---------------- recurrent conv: z = zx[:,t] + conv3x3(h, Wh) --------------
// grid: (ocb=8, tile=8, b=4)
__global__ __launch_bounds__(256, 2) void convh_kernel(const float* __restrict__ Wh, int t) {
    extern __shared__ float sm[];
    float* s_in = sm;                 // 32 * 613 (one 32-channel chunk)
    float* s_w  = sm + 32 * PS;       // 9216

    int ocb  = blockIdx.x;
    int tile = blockIdx.y;
    int b    = blockIdx.z;
    int tid  = threadIdx.x;
    int ty0 = (tile >> 1) * 16, tx0 = (tile & 1) * 32;
    int oc0 = ocb * 32;
    int px = tid & 31, py = tid >> 5;
    int y1 = ty0 + py, y2 = y1 + 8, x = tx0 + px;

    float acc1[32], acc2[32];
    const float4* z1 = (const float4*)(g_zx + (((((size_t)b * TT) + t) * HH + y1) * WW + x) * OC + oc0);
    const float4* z2 = (const float4*)(g_zx + (((((size_t)b * TT) + t) * HH + y2) * WW + x) * OC + oc0);
    #pragma unroll
    for (int j = 0; j < 8; j++) {
        float4 v = z1[j];
        acc1[4*j+0] = v.x; acc1[4*j+1] = v.y; acc1[4*j+2] = v.z; acc1[4*j+3] = v.w;
        float4 w = z2[j];
        acc2[4*j+0] = w.x; acc2[4*j+1] = w.y; acc2[4*j+2] = w.z; acc2[4*j+3] = w.w;
    }

    const float* hin = g_h + (size_t)b * HH * WW * FF;

    for (int ch0 = 0; ch0 < FF; ch0 += 32) {
        if (ch0) __syncthreads();
        // input chunk: 8 channel-quads x 612 halo positions, coalesced float4
        for (int i = tid; i < 8 * HALO; i += 256) {
            int c4 = (i & 7) * 4, sp = i >> 3;
            int ry = sp / 34, rx = sp - ry * 34;
            int gy = ty0 - 1 + ry, gx = tx0 - 1 + rx;
            float4 v = make_float4(0.f, 0.f, 0.f, 0.f);
            if (gy >= 0 && gy < HH && gx >= 0 && gx < WW)
                v = *(const float4*)(hin + ((size_t)gy * WW + gx) * FF + ch0 + c4);
            s_in[(c4+0)*PS + sp] = v.x; s_in[(c4+1)*PS + sp] = v.y;
            s_in[(c4+2)*PS + sp] = v.z; s_in[(c4+3)*PS + sp] = v.w;
        }
        // weight chunk [kp][ic_local 32][oc32]
        for (int i = tid; i < 9216; i += 256) {
            int oc = i & 31, rest = i >> 5, kp = rest >> 5, icl = rest & 31;
            s_w[i] = Wh[((size_t)kp * FF + ch0 + icl) * OC + oc0 + oc];
        }
        __syncthreads();

        #pragma unroll
        for (int kp = 0; kp < 9; kp++) {
            int ky = kp / 3, kx = kp - 3 * ky;
            int spb = (py + ky) * 34 + px + kx;
            const float* wk = s_w + kp * 1024;
            #pragma unroll 4
            for (int icl = 0; icl < 32; icl++) {
                float a1 = s_in[icl * PS + spb];
                float a2 = s_in[icl * PS + spb + 272];
                const float4* w4 = (const float4*)(wk + icl * 32);
                #pragma unroll
                for (int j = 0; j < 8; j++) {
                    float4 w = w4[j];
                    acc1[4*j+0] += a1 * w.x; acc1[4*j+1] += a1 * w.y;
                    acc1[4*j+2] += a1 * w.z; acc1[4*j+3] += a1 * w.w;
                    acc2[4*j+0] += a2 * w.x; acc2[4*j+1] += a2 * w.y;
                    acc2[4*j+2] += a2 * w.z; acc2[4*j+3] += a2 * w.w;
                }
            }
        }
    }

    float* o1 = g_z + (((size_t)b * HH + y1) * WW + x) * OC + oc0;
    float* o2 = g_z + (((size_t)b * HH + y2) * WW + x) * OC + oc0;
    #pragma unroll
    for (int j = 0; j < 8; j++) {
        ((float4*)o1)[j] = make_float4(acc1[4*j], acc1[4*j+1], acc1[4*j+2], acc1[4*j+3]);
        ((float4*)o2)[j] = make_float4(acc2[4*j], acc2[4*j+1], acc2[4*j+2], acc2[4*j+3]);
    }
}

// ---------------- LSTM gates + MaxPool(2x2) fused ---------------------------
__global__ void gatepool_kernel(float* __restrict__ out, int t) {
    int i = blockIdx.x * blockDim.x + threadIdx.x;   // B*32*32*F = 262144
    if (i >= BB * 32 * 32 * FF) return;
    int f = i & 63;
    int r = i >> 6;
    int xo = r & 31; r >>= 5;
    int yo = r & 31;
    int b  = r >> 5;

    float m = -1e30f;
    #pragma unroll
    for (int dy = 0; dy < 2; dy++) {
        #pragma unroll
        for (int dx = 0; dx < 2; dx++) {
            size_t pix = ((size_t)b * HH + (yo * 2 + dy)) * WW + (xo * 2 + dx);
            const float* z = g_z + pix * OC;
            float zi = z[f], zf = z[64 + f], zc = z[128 + f], zo_ = z[192 + f];
            float ig = __saturatef(0.2f * zi + 0.5f);
            float fg = __saturatef(0.2f * zf + 0.5f);
            float og = __saturatef(0.2f * zo_ + 0.5f);
            size_t hi = pix * FF + f;
            float c  = fg * g_c[hi] + ig * tanhf(zc);
            g_c[hi] = c;
            float h = og * tanhf(c);
            g_h[hi] = h;
            m = fmaxf(m, h);
        }
    }
    out[(((((size_t)b * TT) + t) * 32 + yo) * 32 + xo) * FF + f] = m;
}

// ---------------- launch ----------------------------------------------------
extern "C" void kernel_launch(void* const* d_in, const int* in_sizes, int n_in,
                              void* d_out, int out_size) {
    const float* x     = (const float*)d_in[0];
    const float* gamma = (const float*)d_in[1];
    const float* beta  = (const float*)d_in[2];
    const float* Wx    = (const float*)d_in[3];
    const float* Wh    = (const float*)d_in[4];
    const float* bias  = (const float*)d_in[5];
    float* out = (float*)d_out;

    const int SMEM = (32 * PS + 9 * 32 * 32) * 4;   // 115328 B
    cudaFuncSetAttribute(convx_kernel, cudaFuncAttributeMaxDynamicSharedMemorySize, SMEM);
    cudaFuncSetAttribute(convh_kernel, cudaFuncAttributeMaxDynamicSharedMemorySize, SMEM);

    // LayerNorm
    ln_kernel<<<(BB * TT * HH * WW) / 8, 256>>>(x, gamma, beta);

    // zero h, c (must happen every call: deterministic)
    zero_hc_kernel<<<(BB * HH * WW * FF + 255) / 256, 256>>>();

    // input conv over all timesteps at once
    convx_kernel<<<dim3(8, 8, BB * TT), 256, SMEM>>>(Wx, bias);

    // recurrent loop
    for (int t = 0; t < TT; t++) {
        convh_kernel<<<dim3(8, 8, BB), 256, SMEM>>>(Wh, t);
        gatepool_kernel<<<(BB * 32 * 32 * FF + 255) / 256, 256>>>(out, t);
    }
}